// round 12
// baseline (speedup 1.0000x reference)
#include <cuda_runtime.h>
#include <cuda_bf16.h>
#include <cstdint>
#include <cstddef>

#define N_NODES 50000
#define NUM_REL 8
#define IN_DIM  128
#define HID     256
#define E_EDGES 1600000
#define M_DEC   200000
#define NKEYS   (N_NODES * NUM_REL)      // 400000

// ---------------------------------------------------------------------------
// Device scratch. Packed format ("ps32"): one uint32 per element =
// (bf16(lo) << 16) | bf16(hi), hi = bf16(x), lo = bf16(x - float(hi)).
// ---------------------------------------------------------------------------
__device__ int      g_deg[NKEYS];
__device__ int      g_off[NKEYS];
__device__ int      g_cur[NKEYS];
__device__ int      g_srcs[E_EDGES];
__device__ int      g_bsums[512];
__device__ uint32_t g_A[(size_t)N_NODES * (HID + NUM_REL * HID)];   // packed, N x 2304 (layer1: N x 1152)
__device__ uint32_t g_B1[1152 * HID];            // layer1 weights [k][n] packed
__device__ uint32_t g_B2[2304 * HID];            // layer2 weights [k][n] packed
__device__ uint32_t g_Bd[HID * 2 * HID];         // decoder W1' (256 x 512) packed
__device__ uint32_t g_Bw2[HID * (HID / 2)];      // decoder W2  (256 x 128) packed
__device__ float    g_hp[(size_t)N_NODES * HID];
__device__ float    g_h1[(size_t)N_NODES * HID];                    // fp32 h1 (dense, L2-hot)
__device__ uint32_t g_hP[(size_t)N_NODES * HID];                    // packed final h
__device__ float    g_P [(size_t)N_NODES * 2 * HID];                // 50000 x 512
__device__ uint32_t g_Z1[(size_t)M_DEC * HID];                      // packed
__device__ float    g_Z2[(size_t)M_DEC * (HID / 2)];

// ---------------------------------------------------------------------------
__device__ __forceinline__ uint32_t bf16_split_pack(float x) {
    __nv_bfloat16 h = __float2bfloat16(x);
    float hf = __bfloat162float(h);
    __nv_bfloat16 l = __float2bfloat16(x - hf);
    return ((uint32_t)__bfloat16_as_ushort(l) << 16) | (uint32_t)__bfloat16_as_ushort(h);
}

__global__ void zero_int_kernel(int* __restrict__ p, int n4) {
    int i = blockIdx.x * blockDim.x + threadIdx.x;
    if (i < n4) ((int4*)p)[i] = make_int4(0, 0, 0, 0);
}

// ---------------------------------------------------------------------------
// CSR build over keys (dst*8 + rel)
// ---------------------------------------------------------------------------
__global__ void hist_kernel(const int* __restrict__ ei, const int* __restrict__ et) {
    int e = blockIdx.x * blockDim.x + threadIdx.x;
    if (e >= E_EDGES) return;
    int key = ei[E_EDGES + e] * NUM_REL + et[e];
    atomicAdd(&g_deg[key], 1);
}

__global__ void scan1_kernel(const int* __restrict__ in, int* __restrict__ out, int n) {
    __shared__ int s[256];
    int t = threadIdx.x;
    int base = blockIdx.x * 1024 + t * 4;
    int v0 = 0, v1 = 0, v2 = 0, v3 = 0;
    if (base + 0 < n) v0 = in[base + 0];
    if (base + 1 < n) v1 = in[base + 1];
    if (base + 2 < n) v2 = in[base + 2];
    if (base + 3 < n) v3 = in[base + 3];
    int tsum = v0 + v1 + v2 + v3;
    s[t] = tsum;
    __syncthreads();
    for (int o = 1; o < 256; o <<= 1) {
        int x = (t >= o) ? s[t - o] : 0;
        __syncthreads();
        s[t] += x;
        __syncthreads();
    }
    int excl = s[t] - tsum;
    if (t == 255) g_bsums[blockIdx.x] = s[255];
    if (base + 0 < n) out[base + 0] = excl;
    if (base + 1 < n) out[base + 1] = excl + v0;
    if (base + 2 < n) out[base + 2] = excl + v0 + v1;
    if (base + 3 < n) out[base + 3] = excl + v0 + v1 + v2;
}

__global__ void scan2_kernel(int nb) {
    __shared__ int s[512];
    int t = threadIdx.x;
    int v = (t < nb) ? g_bsums[t] : 0;
    s[t] = v;
    __syncthreads();
    for (int o = 1; o < 512; o <<= 1) {
        int x = (t >= o) ? s[t - o] : 0;
        __syncthreads();
        s[t] += x;
        __syncthreads();
    }
    if (t < nb) g_bsums[t] = s[t] - v;   // exclusive
}

__global__ void scan3_kernel(int* __restrict__ off, int* __restrict__ cur, int n) {
    int i = blockIdx.x * blockDim.x + threadIdx.x;
    if (i >= n) return;
    int o = off[i] + g_bsums[i >> 10];
    off[i] = o;
    cur[i] = o;
}

__global__ void fill_kernel(const int* __restrict__ ei, const int* __restrict__ et) {
    int e = blockIdx.x * blockDim.x + threadIdx.x;
    if (e >= E_EDGES) return;
    int key = ei[E_EDGES + e] * NUM_REL + et[e];
    int p = atomicAdd(&g_cur[key], 1);
    g_srcs[p] = ei[e];
}

// ---------------------------------------------------------------------------
// Gather-reduce aggregation (one warp per (node, rel) key) → packed mean into
// g_A[n, (1+r)*DIN : (2+r)*DIN].
// ---------------------------------------------------------------------------
template <int DIN>
__global__ void gather_agg_kernel(const float* __restrict__ feat) {
    const int K = DIN * (NUM_REL + 1);
    int w = (blockIdx.x * blockDim.x + threadIdx.x) >> 5;
    int lane = threadIdx.x & 31;
    if (w >= NKEYS) return;
    int n = w >> 3;
    int r = w & 7;
    int off = g_off[w];
    int cnt = g_deg[w];

    float4 a0 = make_float4(0.f, 0.f, 0.f, 0.f);
    float4 a1 = make_float4(0.f, 0.f, 0.f, 0.f);

    int i = 0;
    for (; i + 2 <= cnt; i += 2) {
        int s0 = g_srcs[off + i];
        int s1 = g_srcs[off + i + 1];
        const float4* p0 = (const float4*)(feat + (size_t)s0 * DIN) + lane;
        const float4* p1 = (const float4*)(feat + (size_t)s1 * DIN) + lane;
        float4 v0 = __ldg(p0);
        float4 v1 = __ldg(p1);
        float4 u0, u1;
        if (DIN == 256) { u0 = __ldg(p0 + 32); u1 = __ldg(p1 + 32); }
        a0.x += v0.x + v1.x; a0.y += v0.y + v1.y;
        a0.z += v0.z + v1.z; a0.w += v0.w + v1.w;
        if (DIN == 256) {
            a1.x += u0.x + u1.x; a1.y += u0.y + u1.y;
            a1.z += u0.z + u1.z; a1.w += u0.w + u1.w;
        }
    }
    if (i < cnt) {
        int s0 = g_srcs[off + i];
        const float4* p0 = (const float4*)(feat + (size_t)s0 * DIN) + lane;
        float4 v0 = __ldg(p0);
        a0.x += v0.x; a0.y += v0.y; a0.z += v0.z; a0.w += v0.w;
        if (DIN == 256) {
            float4 u0 = __ldg(p0 + 32);
            a1.x += u0.x; a1.y += u0.y; a1.z += u0.z; a1.w += u0.w;
        }
    }

    float sc = 1.0f / fmaxf((float)cnt, 1.0f);
    uint4 o0;
    o0.x = bf16_split_pack(a0.x * sc);
    o0.y = bf16_split_pack(a0.y * sc);
    o0.z = bf16_split_pack(a0.z * sc);
    o0.w = bf16_split_pack(a0.w * sc);
    uint4* dst = (uint4*)(g_A + (size_t)n * K + (1 + r) * DIN) + lane;
    *dst = o0;
    if (DIN == 256) {
        uint4 o1;
        o1.x = bf16_split_pack(a1.x * sc);
        o1.y = bf16_split_pack(a1.y * sc);
        o1.z = bf16_split_pack(a1.z * sc);
        o1.w = bf16_split_pack(a1.w * sc);
        *(dst + 32) = o1;
    }
}

// Layer-1 root copy: x packed into A[:, 0:128] (stride 1152)
__global__ void copy_feat1_kernel(const float* __restrict__ feat) {
    const int K = 1152;
    const int L = IN_DIM / 4;
    int idx = blockIdx.x * blockDim.x + threadIdx.x;
    if (idx >= N_NODES * L) return;
    int n = idx / L;
    int j = idx % L;
    float4 v = *((const float4*)(feat + (size_t)n * IN_DIM) + j);
    uint4 o;
    o.x = bf16_split_pack(v.x);
    o.y = bf16_split_pack(v.y);
    o.z = bf16_split_pack(v.z);
    o.w = bf16_split_pack(v.w);
    *((uint4*)(g_A + (size_t)n * K) + j) = o;
}

// ---------------------------------------------------------------------------
// Weight builders ([k][n] packed), each to its own buffer
// ---------------------------------------------------------------------------
__global__ void build_B_kernel(const float* __restrict__ root,
                               const float* __restrict__ W, int Kin,
                               uint32_t* __restrict__ out) {
    int total = Kin * (NUM_REL + 1) * HID;
    int idx = blockIdx.x * blockDim.x + threadIdx.x;
    if (idx >= total) return;
    int rootN = Kin * HID;
    float v = (idx < rootN) ? root[idx] : W[idx - rootN];
    out[idx] = bf16_split_pack(v);
}

// Decoder B' (256 x 512): cols 0..255 = mw1_top, 256..511 = mw1_bot
__global__ void build_Bdec_kernel(const float* __restrict__ mw1) {
    int idx = blockIdx.x * blockDim.x + threadIdx.x;   // 256*512
    if (idx >= HID * 2 * HID) return;
    int k = idx >> 9;
    int n = idx & 511;
    float v = (n < HID) ? mw1[k * HID + n] : mw1[(HID + k) * HID + (n - HID)];
    g_Bd[idx] = bf16_split_pack(v);
}

__global__ void pack_w2_kernel(const float* __restrict__ mw2) {
    int idx = blockIdx.x * blockDim.x + threadIdx.x;
    if (idx >= HID * (HID / 2)) return;
    g_Bw2[idx] = bf16_split_pack(mw2[idx]);
}

// ---------------------------------------------------------------------------
// Common GEMM pieces
// ---------------------------------------------------------------------------
__device__ __forceinline__ void cp16(uint32_t smem, const void* g) {
    asm volatile("cp.async.cg.shared.global [%0], [%1], 16;" :: "r"(smem), "l"(g));
}

#define MMA_BF16(d, a, b)                                                     \
    asm volatile("mma.sync.aligned.m16n8k16.row.col.f32.bf16.bf16.f32 "       \
                 "{%0,%1,%2,%3}, {%4,%5,%6,%7}, {%8,%9}, {%0,%1,%2,%3};"      \
                 : "+f"(d[0]), "+f"(d[1]), "+f"(d[2]), "+f"(d[3])             \
                 : "r"(a[0]), "r"(a[1]), "r"(a[2]), "r"(a[3]),                \
                   "r"(b[0]), "r"(b[1]))

// ---------------------------------------------------------------------------
// WIDE GEMM: 128x256 tile per CTA, 512 threads, BK=16, 2-stage cp.async.
// A [M,K] packed u32, B [K,N] packed u32 (N multiple of 256), C fp32 + bias.
// Warp grid 4x4; warp tile 32x64 (2 m-tiles x 8 n-tiles). A fragments hoisted,
// B fragments streamed per n-tile to bound register pressure.
// ---------------------------------------------------------------------------
#define WA_STR 20    // u32 per A-smem row (16 + 4 pad)
#define WB_STR 260   // u32 per B-smem row (256 + 4 pad)
#define WA_TILE (128 * WA_STR)
#define WB_TILE (16 * WB_STR)
#define W_SMEM_U32 (2 * (WA_TILE + WB_TILE))

__global__ __launch_bounds__(512, 1)
void gemm_wide_kernel(const uint32_t* __restrict__ A, const uint32_t* __restrict__ B,
                      float* __restrict__ C, const float* __restrict__ bias,
                      int M, int N, int K) {
    extern __shared__ uint32_t wsm[];
    uint32_t* As[2] = {wsm, wsm + WA_TILE};
    uint32_t* Bs[2] = {wsm + 2 * WA_TILE, wsm + 2 * WA_TILE + WB_TILE};

    const int tid  = threadIdx.x;
    const int warp = tid >> 5, lane = tid & 31;
    const int gid  = lane >> 2, tig = lane & 3;
    const int wm   = (warp & 3) * 32;        // warp row base (0..96)
    const int wn   = (warp >> 2) * 64;       // warp col base (0..192)
    const int brow = blockIdx.y * 128, bcol = blockIdx.x * 256;

    float acc[2][8][4];
#pragma unroll
    for (int i = 0; i < 2; i++)
#pragma unroll
        for (int j = 0; j < 8; j++)
#pragma unroll
            for (int c = 0; c < 4; c++) acc[i][j][c] = 0.f;

    // staging: A — thread covers row (tid>>2), u32 cols [(tid&3)*4, +4)
    //          B — thread covers k-row (tid>>5), u32 cols [(tid&31)*8, +8)
    const int ar = tid >> 2;
    const int ac = (tid & 3) * 4;
    const int br = tid >> 5;
    const int bc = (tid & 31) * 8;

    const int arow_g = min(brow + ar, M - 1);
    const uint32_t* ag = A + (size_t)arow_g * K + ac;
    const uint32_t* bg = B + (size_t)br * N + bcol + bc;

    uint32_t a_sm[2], b_sm[2];
#pragma unroll
    for (int s = 0; s < 2; s++) {
        a_sm[s] = (uint32_t)__cvta_generic_to_shared(&As[s][ar * WA_STR + ac]);
        b_sm[s] = (uint32_t)__cvta_generic_to_shared(&Bs[s][br * WB_STR + bc]);
    }

    const int ntiles = K >> 4;

    cp16(a_sm[0], ag);
    cp16(b_sm[0],      bg);
    cp16(b_sm[0] + 16, bg + 4);
    asm volatile("cp.async.commit_group;");

    for (int t = 0; t < ntiles; t++) {
        if (t + 1 < ntiles) {
            int k0 = (t + 1) << 4;
            int s = (t + 1) & 1;
            cp16(a_sm[s], ag + k0);
            cp16(b_sm[s],      bg + (size_t)k0 * N);
            cp16(b_sm[s] + 16, bg + (size_t)k0 * N + 4);
            asm volatile("cp.async.commit_group;");
            asm volatile("cp.async.wait_group 1;");
        } else {
            asm volatile("cp.async.wait_group 0;");
        }
        __syncthreads();

        const uint32_t* as = As[t & 1];
        const uint32_t* bs = Bs[t & 1];

        // hoist A fragments (2 m-tiles)
        uint32_t ah[2][4], al[2][4];
#pragma unroll
        for (int mt = 0; mt < 2; mt++) {
            int m0 = wm + mt * 16 + gid;
            uint2 p0 = *(const uint2*)&as[m0 * WA_STR + tig * 2];
            uint2 p1 = *(const uint2*)&as[(m0 + 8) * WA_STR + tig * 2];
            uint2 p2 = *(const uint2*)&as[m0 * WA_STR + tig * 2 + 8];
            uint2 p3 = *(const uint2*)&as[(m0 + 8) * WA_STR + tig * 2 + 8];
            ah[mt][0] = __byte_perm(p0.x, p0.y, 0x5410);
            ah[mt][1] = __byte_perm(p1.x, p1.y, 0x5410);
            ah[mt][2] = __byte_perm(p2.x, p2.y, 0x5410);
            ah[mt][3] = __byte_perm(p3.x, p3.y, 0x5410);
            al[mt][0] = __byte_perm(p0.x, p0.y, 0x7632);
            al[mt][1] = __byte_perm(p1.x, p1.y, 0x7632);
            al[mt][2] = __byte_perm(p2.x, p2.y, 0x7632);
            al[mt][3] = __byte_perm(p3.x, p3.y, 0x7632);
        }
        // stream B fragments per n-tile
#pragma unroll
        for (int nt = 0; nt < 8; nt++) {
            int n = wn + nt * 8 + gid;
            uint32_t r0 = bs[(tig * 2 + 0) * WB_STR + n];
            uint32_t r1 = bs[(tig * 2 + 1) * WB_STR + n];
            uint32_t r2 = bs[(tig * 2 + 8) * WB_STR + n];
            uint32_t r3 = bs[(tig * 2 + 9) * WB_STR + n];
            uint32_t bh[2], bl[2];
            bh[0] = __byte_perm(r0, r1, 0x5410);
            bh[1] = __byte_perm(r2, r3, 0x5410);
            bl[0] = __byte_perm(r0, r1, 0x7632);
            bl[1] = __byte_perm(r2, r3, 0x7632);
#pragma unroll
            for (int mt = 0; mt < 2; mt++) {
                MMA_BF16(acc[mt][nt], ah[mt], bh);
                MMA_BF16(acc[mt][nt], ah[mt], bl);
                MMA_BF16(acc[mt][nt], al[mt], bh);
            }
        }
        __syncthreads();
    }

    // ---- epilogue: bias only (no activation for wide GEMM call sites) ----
#pragma unroll
    for (int mt = 0; mt < 2; mt++) {
        int r0 = brow + wm + mt * 16 + gid;
#pragma unroll
        for (int nt = 0; nt < 8; nt++) {
            int c = bcol + wn + nt * 8 + 2 * tig;
            float bb0 = bias ? bias[c] : 0.f;
            float bb1 = bias ? bias[c + 1] : 0.f;
            if (r0 < M)
                *(float2*)(C + (size_t)r0 * N + c) =
                    make_float2(acc[mt][nt][0] + bb0, acc[mt][nt][1] + bb1);
            if (r0 + 8 < M)
                *(float2*)(C + (size_t)(r0 + 8) * N + c) =
                    make_float2(acc[mt][nt][2] + bb0, acc[mt][nt][3] + bb1);
        }
    }
}

// ---------------------------------------------------------------------------
// Narrow GEMM (R6 champion) — used for Z2 (N=128, GELU epilogue).
// ---------------------------------------------------------------------------
#define ASTRIDE 20
#define BSTRIDE 132

__global__ __launch_bounds__(256, 2)
void gemm_ps_kernel(const uint32_t* __restrict__ A, const uint32_t* __restrict__ B,
                    float* __restrict__ C, const float* __restrict__ bias,
                    int M, int N, int K, int act) {
    __shared__ uint32_t As[2][128 * ASTRIDE];
    __shared__ uint32_t Bs[2][16 * BSTRIDE];

    const int tid  = threadIdx.x;
    const int warp = tid >> 5, lane = tid & 31;
    const int gid  = lane >> 2, tig = lane & 3;
    const int wm   = (warp & 1) * 64, wn = (warp >> 1) * 32;
    const int brow = blockIdx.y * 128, bcol = blockIdx.x * 128;

    float acc[4][4][4];
#pragma unroll
    for (int i = 0; i < 4; i++)
#pragma unroll
        for (int j = 0; j < 4; j++)
#pragma unroll
            for (int c = 0; c < 4; c++) acc[i][j][c] = 0.f;

    const int ar = tid >> 1;
    const int ac = (tid & 1) * 8;
    const int br = tid >> 4;
    const int bc = (tid & 15) * 8;

    const int arow_g = min(brow + ar, M - 1);
    const uint32_t* ag = A + (size_t)arow_g * K + ac;
    const uint32_t* bg = B + (size_t)br * N + bcol + bc;

    const uint32_t a_sm0 = (uint32_t)__cvta_generic_to_shared(&As[0][ar * ASTRIDE + ac]);
    const uint32_t a_sm1 = (uint32_t)__cvta_generic_to_shared(&As[1][ar * ASTRIDE + ac]);
    const uint32_t b_sm0 = (uint32_t)__cvta_generic_to_shared(&Bs[0][br * BSTRIDE + bc]);
    const uint32_t b_sm1 = (uint32_t)__cvta_generic_to_shared(&Bs[1][br * BSTRIDE + bc]);

    const int ntiles = K >> 4;

    cp16(a_sm0,      ag);
    cp16(a_sm0 + 16, ag + 4);
    cp16(b_sm0,      bg);
    cp16(b_sm0 + 16, bg + 4);
    asm volatile("cp.async.commit_group;");

    for (int t = 0; t < ntiles; t++) {
        if (t + 1 < ntiles) {
            int k0 = (t + 1) << 4;
            uint32_t asm_ = ((t + 1) & 1) ? a_sm1 : a_sm0;
            uint32_t bsm_ = ((t + 1) & 1) ? b_sm1 : b_sm0;
            cp16(asm_,      ag + k0);
            cp16(asm_ + 16, ag + k0 + 4);
            cp16(bsm_,      bg + (size_t)k0 * N);
            cp16(bsm_ + 16, bg + (size_t)k0 * N + 4);
            asm volatile("cp.async.commit_group;");
            asm volatile("cp.async.wait_group 1;");
        } else {
            asm volatile("cp.async.wait_group 0;");
        }
        __syncthreads();

        const uint32_t* as = As[t & 1];
        const uint32_t* bs = Bs[t & 1];

        uint32_t bh[4][2], bl[4][2];
#pragma unroll
        for (int nt = 0; nt < 4; nt++) {
            int n = wn + nt * 8 + gid;
            uint32_t r0 = bs[(tig * 2 + 0) * BSTRIDE + n];
            uint32_t r1 = bs[(tig * 2 + 1) * BSTRIDE + n];
            uint32_t r2 = bs[(tig * 2 + 8) * BSTRIDE + n];
            uint32_t r3 = bs[(tig * 2 + 9) * BSTRIDE + n];
            bh[nt][0] = __byte_perm(r0, r1, 0x5410);
            bh[nt][1] = __byte_perm(r2, r3, 0x5410);
            bl[nt][0] = __byte_perm(r0, r1, 0x7632);
            bl[nt][1] = __byte_perm(r2, r3, 0x7632);
        }
#pragma unroll
        for (int mt = 0; mt < 4; mt++) {
            int m0 = wm + mt * 16 + gid;
            uint2 p0 = *(const uint2*)&as[m0 * ASTRIDE + tig * 2];
            uint2 p1 = *(const uint2*)&as[(m0 + 8) * ASTRIDE + tig * 2];
            uint2 p2 = *(const uint2*)&as[m0 * ASTRIDE + tig * 2 + 8];
            uint2 p3 = *(const uint2*)&as[(m0 + 8) * ASTRIDE + tig * 2 + 8];
            uint32_t ah[4] = {__byte_perm(p0.x, p0.y, 0x5410), __byte_perm(p1.x, p1.y, 0x5410),
                              __byte_perm(p2.x, p2.y, 0x5410), __byte_perm(p3.x, p3.y, 0x5410)};
            uint32_t al[4] = {__byte_perm(p0.x, p0.y, 0x7632), __byte_perm(p1.x, p1.y, 0x7632),
                              __byte_perm(p2.x, p2.y, 0x7632), __byte_perm(p3.x, p3.y, 0x7632)};
#pragma unroll
            for (int nt = 0; nt < 4; nt++) {
                MMA_BF16(acc[mt][nt], ah, bh[nt]);
                MMA_BF16(acc[mt][nt], ah, bl[nt]);
                MMA_BF16(acc[mt][nt], al, bh[nt]);
            }
        }
        __syncthreads();
    }

#pragma unroll
    for (int mt = 0; mt < 4; mt++) {
        int r0 = brow + wm + mt * 16 + gid;
#pragma unroll
        for (int nt = 0; nt < 4; nt++) {
            int c = bcol + wn + nt * 8 + 2 * tig;
            float bb0 = bias ? bias[c] : 0.f;
            float bb1 = bias ? bias[c + 1] : 0.f;
            float v0 = acc[mt][nt][0] + bb0;
            float v1 = acc[mt][nt][1] + bb1;
            float v2 = acc[mt][nt][2] + bb0;
            float v3 = acc[mt][nt][3] + bb1;
            if (act == 1) {
                const float is2 = 0.70710678118654752f;
                v0 = 0.5f * v0 * (1.0f + erff(v0 * is2));
                v1 = 0.5f * v1 * (1.0f + erff(v1 * is2));
                v2 = 0.5f * v2 * (1.0f + erff(v2 * is2));
                v3 = 0.5f * v3 * (1.0f + erff(v3 * is2));
            }
            if (r0 < M)
                *(float2*)(C + (size_t)r0 * N + c) = make_float2(v0, v1);
            if (r0 + 8 < M)
                *(float2*)(C + (size_t)(r0 + 8) * N + c) = make_float2(v2, v3);
        }
    }
}

// ---------------------------------------------------------------------------
// Layer 1: ReLU + LN → fp32 h1 AND packed A-root (stride 2304) [fused copy_feat2]
// ---------------------------------------------------------------------------
__global__ void relu_ln1_kernel(const float* __restrict__ hp,
                                const float* __restrict__ g,
                                const float* __restrict__ b,
                                float* __restrict__ out) {
    int row = blockIdx.x;
    int tid = threadIdx.x;   // 256 == HID
    float v = fmaxf(hp[(size_t)row * HID + tid], 0.0f);

    __shared__ float red[8];
    __shared__ float s_mu, s_rs;

    float s = v;
#pragma unroll
    for (int o = 16; o; o >>= 1) s += __shfl_xor_sync(0xFFFFFFFFu, s, o);
    if ((tid & 31) == 0) red[tid >> 5] = s;
    __syncthreads();
    if (tid == 0) {
        float t = 0.f;
#pragma unroll
        for (int i = 0; i < 8; i++) t += red[i];
        s_mu = t / (float)HID;
    }
    __syncthreads();

    float d = v - s_mu;
    float s2 = d * d;
#pragma unroll
    for (int o = 16; o; o >>= 1) s2 += __shfl_xor_sync(0xFFFFFFFFu, s2, o);
    if ((tid & 31) == 0) red[tid >> 5] = s2;
    __syncthreads();
    if (tid == 0) {
        float t = 0.f;
#pragma unroll
        for (int i = 0; i < 8; i++) t += red[i];
        s_rs = rsqrtf(t / (float)HID + 1e-5f);
    }
    __syncthreads();

    float o = d * s_rs * g[tid] + b[tid];
    out[(size_t)row * HID + tid] = o;                       // fp32 h1 (dense)
    g_A[(size_t)row * 2304 + tid] = bf16_split_pack(o);     // packed A root
}

// Layer 2: packed(resid + LN(relu(hp)))
__global__ void relu_ln_pack_kernel(const float* __restrict__ hp,
                                    const float* __restrict__ g,
                                    const float* __restrict__ b,
                                    uint32_t* __restrict__ outp,
                                    const float* __restrict__ resid) {
    int row = blockIdx.x;
    int tid = threadIdx.x;
    float v = fmaxf(hp[(size_t)row * HID + tid], 0.0f);

    __shared__ float red[8];
    __shared__ float s_mu, s_rs;

    float s = v;
#pragma unroll
    for (int o = 16; o; o >>= 1) s += __shfl_xor_sync(0xFFFFFFFFu, s, o);
    if ((tid & 31) == 0) red[tid >> 5] = s;
    __syncthreads();
    if (tid == 0) {
        float t = 0.f;
#pragma unroll
        for (int i = 0; i < 8; i++) t += red[i];
        s_mu = t / (float)HID;
    }
    __syncthreads();

    float d = v - s_mu;
    float s2 = d * d;
#pragma unroll
    for (int o = 16; o; o >>= 1) s2 += __shfl_xor_sync(0xFFFFFFFFu, s2, o);
    if ((tid & 31) == 0) red[tid >> 5] = s2;
    __syncthreads();
    if (tid == 0) {
        float t = 0.f;
#pragma unroll
        for (int i = 0; i < 8; i++) t += red[i];
        s_rs = rsqrtf(t / (float)HID + 1e-5f);
    }
    __syncthreads();

    float o = d * s_rs * g[tid] + b[tid] + resid[(size_t)row * HID + tid];
    outp[(size_t)row * HID + tid] = bf16_split_pack(o);
}

// ---------------------------------------------------------------------------
// Fused decoder stage 1: Z1[m,c] = packed(gelu(P[u][c] + P[v][256+c] + b1[c]))
// ---------------------------------------------------------------------------
__global__ void decode_fuse_kernel(const int* __restrict__ dec,
                                   const float* __restrict__ b1) {
    int idx = blockIdx.x * blockDim.x + threadIdx.x;
    if (idx >= M_DEC * (HID / 4)) return;
    int m = idx >> 6;
    int j = idx & 63;
    int u = dec[m * 2 + 0];
    int v = dec[m * 2 + 1];
    float4 p = __ldg((const float4*)(g_P + (size_t)u * 512) + j);
    float4 q = __ldg((const float4*)(g_P + (size_t)v * 512 + 256) + j);
    float4 bb = *((const float4*)b1 + j);
    const float is2 = 0.70710678118654752f;
    float zx = p.x + q.x + bb.x; zx = 0.5f * zx * (1.0f + erff(zx * is2));
    float zy = p.y + q.y + bb.y; zy = 0.5f * zy * (1.0f + erff(zy * is2));
    float zz = p.z + q.z + bb.z; zz = 0.5f * zz * (1.0f + erff(zz * is2));
    float zw = p.w + q.w + bb.w; zw = 0.5f * zw * (1.0f + erff(zw * is2));
    uint4 o;
    o.x = bf16_split_pack(zx);
    o.y = bf16_split_pack(zy);
    o.z = bf16_split_pack(zz);
    o.w = bf16_split_pack(zw);
    *((uint4*)(g_Z1 + (size_t)m * HID) + j) = o;
}

// ---------------------------------------------------------------------------
__global__ void final_kernel(const float* __restrict__ w3,
                             const float* __restrict__ b3,
                             float* __restrict__ out) {
    long long t = (long long)blockIdx.x * blockDim.x + threadIdx.x;
    int m = (int)(t >> 5);
    int lane = (int)(t & 31);
    if (m >= M_DEC) return;
    float4 z = *(const float4*)(g_Z2 + (size_t)m * 128 + lane * 4);
    const float* w = w3 + lane * 4 * 2;
    float s0 = z.x * w[0] + z.y * w[2] + z.z * w[4] + z.w * w[6];
    float s1 = z.x * w[1] + z.y * w[3] + z.z * w[5] + z.w * w[7];
#pragma unroll
    for (int o = 16; o; o >>= 1) {
        s0 += __shfl_xor_sync(0xFFFFFFFFu, s0, o);
        s1 += __shfl_xor_sync(0xFFFFFFFFu, s1, o);
    }
    if (lane == 0) {
        out[m * 2 + 0] = s0 + b3[0];
        out[m * 2 + 1] = s1 + b3[1];
    }
}

// ---------------------------------------------------------------------------
static inline int blocks_for(long long n, int bs) { return (int)((n + bs - 1) / bs); }

extern "C" void kernel_launch(void* const* d_in, const int* in_sizes, int n_in,
                              void* d_out, int out_size) {
    const float* x     = (const float*)d_in[0];
    const int*   ei    = (const int*)  d_in[1];
    const int*   et    = (const int*)  d_in[2];
    const int*   dec   = (const int*)  d_in[3];
    const float* W1    = (const float*)d_in[4];
    const float* root1 = (const float*)d_in[5];
    const float* b1    = (const float*)d_in[6];
    const float* W2    = (const float*)d_in[7];
    const float* root2 = (const float*)d_in[8];
    const float* b2    = (const float*)d_in[9];
    const float* ln1g  = (const float*)d_in[10];
    const float* ln1b  = (const float*)d_in[11];
    const float* ln2g  = (const float*)d_in[12];
    const float* ln2b  = (const float*)d_in[13];
    const float* mw1   = (const float*)d_in[14];
    const float* mb1   = (const float*)d_in[15];
    const float* mw2   = (const float*)d_in[16];
    const float* mb2   = (const float*)d_in[17];
    const float* mw3   = (const float*)d_in[18];
    const float* mb3   = (const float*)d_in[19];
    float* out = (float*)d_out;

    uint32_t *A, *B1p, *B2p, *Bd, *Bw2, *hP, *Z1;
    float *hp, *h1, *P, *Z2;
    int *deg, *off, *cur;
    cudaGetSymbolAddress((void**)&A,   g_A);
    cudaGetSymbolAddress((void**)&B1p, g_B1);
    cudaGetSymbolAddress((void**)&B2p, g_B2);
    cudaGetSymbolAddress((void**)&Bd,  g_Bd);
    cudaGetSymbolAddress((void**)&Bw2, g_Bw2);
    cudaGetSymbolAddress((void**)&hP,  g_hP);
    cudaGetSymbolAddress((void**)&Z1,  g_Z1);
    cudaGetSymbolAddress((void**)&hp,  g_hp);
    cudaGetSymbolAddress((void**)&h1,  g_h1);
    cudaGetSymbolAddress((void**)&P,   g_P);
    cudaGetSymbolAddress((void**)&Z2,  g_Z2);
    cudaGetSymbolAddress((void**)&deg, g_deg);
    cudaGetSymbolAddress((void**)&off, g_off);
    cudaGetSymbolAddress((void**)&cur, g_cur);

    const int W_SMEM = W_SMEM_U32 * 4;   // ~53.8 KB dynamic
    cudaFuncSetAttribute(gemm_wide_kernel, cudaFuncAttributeMaxDynamicSharedMemorySize, W_SMEM);

    // ===================== CSR build =====================
    zero_int_kernel<<<blocks_for(NKEYS / 4, 256), 256>>>(deg, NKEYS / 4);
    hist_kernel<<<blocks_for(E_EDGES, 256), 256>>>(ei, et);
    int nblk = (NKEYS + 1023) / 1024;
    scan1_kernel<<<nblk, 256>>>(deg, off, NKEYS);
    scan2_kernel<<<1, 512>>>(nblk);
    scan3_kernel<<<blocks_for(NKEYS, 256), 256>>>(off, cur, NKEYS);
    fill_kernel<<<blocks_for(E_EDGES, 256), 256>>>(ei, et);

    // ===================== Weight packs + layer-1 root =====================
    copy_feat1_kernel<<<blocks_for(N_NODES * (IN_DIM / 4), 256), 256>>>(x);
    build_B_kernel<<<blocks_for(1152 * HID, 256), 256>>>(root1, W1, IN_DIM, B1p);
    build_B_kernel<<<blocks_for(2304 * HID, 256), 256>>>(root2, W2, HID, B2p);
    build_Bdec_kernel<<<blocks_for(2 * HID * HID, 256), 256>>>(mw1);
    pack_w2_kernel<<<blocks_for(HID * (HID / 2), 256), 256>>>(mw2);

    // ===================== Layer 1 (K = 1152) =====================
    gather_agg_kernel<IN_DIM><<<blocks_for((long long)NKEYS * 32, 256), 256>>>(x);
    {
        dim3 grid(1, (N_NODES + 127) / 128);
        gemm_wide_kernel<<<grid, 512, W_SMEM>>>(A, B1p, hp, b1, N_NODES, HID, 1152);
    }
    relu_ln1_kernel<<<N_NODES, HID>>>(hp, ln1g, ln1b, h1);   // also packs A root

    // ===================== Layer 2 (K = 2304) =====================
    gather_agg_kernel<HID><<<blocks_for((long long)NKEYS * 32, 256), 256>>>(h1);
    {
        dim3 grid(1, (N_NODES + 127) / 128);
        gemm_wide_kernel<<<grid, 512, W_SMEM>>>(A, B2p, hp, b2, N_NODES, HID, 2304);
    }
    relu_ln_pack_kernel<<<N_NODES, HID>>>(hp, ln2g, ln2b, hP, h1);

    // ===================== Decoder =====================
    {
        dim3 gp(2, (N_NODES + 127) / 128);
        gemm_wide_kernel<<<gp, 512, W_SMEM>>>(hP, Bd, P, nullptr, N_NODES, 2 * HID, HID);

        decode_fuse_kernel<<<blocks_for((long long)M_DEC * (HID / 4), 256), 256>>>(dec, mb1);

        dim3 g2(1, (M_DEC + 127) / 128);
        gemm_ps_kernel<<<g2, 256>>>(Z1, Bw2, Z2, mb2, M_DEC, HID / 2, HID, 1);

        final_kernel<<<blocks_for((long long)M_DEC * 32, 256), 256>>>(mw3, mb3, out);
    }
}

// round 13
// speedup vs baseline: 1.1758x; 1.1758x over previous
#include <cuda_runtime.h>
#include <cuda_bf16.h>
#include <cstdint>
#include <cstddef>

#define N_NODES 50000
#define NUM_REL 8
#define IN_DIM  128
#define HID     256
#define E_EDGES 1600000
#define M_DEC   200000
#define NKEYS   (N_NODES * NUM_REL)      // 400000

// ---------------------------------------------------------------------------
// Device scratch. Packed format ("ps32"): one uint32 per element =
// (bf16(lo) << 16) | bf16(hi), hi = bf16(x), lo = bf16(x - float(hi)).
// ---------------------------------------------------------------------------
__device__ int      g_deg[NKEYS];
__device__ int      g_off[NKEYS];
__device__ int      g_cur[NKEYS];
__device__ int      g_srcs[E_EDGES];
__device__ int      g_bsums[512];
__device__ uint32_t g_A[(size_t)N_NODES * (HID + NUM_REL * HID)];   // packed, N x 2304 (layer1: N x 1152)
__device__ uint32_t g_B1[1152 * HID];            // layer1 weights [k][n] packed
__device__ uint32_t g_B2[2304 * HID];            // layer2 weights [k][n] packed
__device__ uint32_t g_Bd[HID * 2 * HID];         // decoder W1' (256 x 512) packed
__device__ uint32_t g_Bw2[HID * (HID / 2)];      // decoder W2  (256 x 128) packed
__device__ float    g_hp[(size_t)N_NODES * HID];
__device__ float    g_h1[(size_t)N_NODES * HID];                    // fp32 h1 (dense, L2-hot)
__device__ uint32_t g_hP[(size_t)N_NODES * HID];                    // packed final h
__device__ float    g_P [(size_t)N_NODES * 2 * HID];                // 50000 x 512
__device__ uint32_t g_Z1[(size_t)M_DEC * HID];                      // packed
__device__ float    g_Z2[(size_t)M_DEC * (HID / 2)];

// ---------------------------------------------------------------------------
__device__ __forceinline__ uint32_t bf16_split_pack(float x) {
    __nv_bfloat16 h = __float2bfloat16(x);
    float hf = __bfloat162float(h);
    __nv_bfloat16 l = __float2bfloat16(x - hf);
    return ((uint32_t)__bfloat16_as_ushort(l) << 16) | (uint32_t)__bfloat16_as_ushort(h);
}

__global__ void zero_int_kernel(int* __restrict__ p, int n4) {
    int i = blockIdx.x * blockDim.x + threadIdx.x;
    if (i < n4) ((int4*)p)[i] = make_int4(0, 0, 0, 0);
}

// ---------------------------------------------------------------------------
// CSR build over keys (dst*8 + rel)
// ---------------------------------------------------------------------------
__global__ void hist_kernel(const int* __restrict__ ei, const int* __restrict__ et) {
    int e = blockIdx.x * blockDim.x + threadIdx.x;
    if (e >= E_EDGES) return;
    int key = ei[E_EDGES + e] * NUM_REL + et[e];
    atomicAdd(&g_deg[key], 1);
}

__global__ void scan1_kernel(const int* __restrict__ in, int* __restrict__ out, int n) {
    __shared__ int s[256];
    int t = threadIdx.x;
    int base = blockIdx.x * 1024 + t * 4;
    int v0 = 0, v1 = 0, v2 = 0, v3 = 0;
    if (base + 0 < n) v0 = in[base + 0];
    if (base + 1 < n) v1 = in[base + 1];
    if (base + 2 < n) v2 = in[base + 2];
    if (base + 3 < n) v3 = in[base + 3];
    int tsum = v0 + v1 + v2 + v3;
    s[t] = tsum;
    __syncthreads();
    for (int o = 1; o < 256; o <<= 1) {
        int x = (t >= o) ? s[t - o] : 0;
        __syncthreads();
        s[t] += x;
        __syncthreads();
    }
    int excl = s[t] - tsum;
    if (t == 255) g_bsums[blockIdx.x] = s[255];
    if (base + 0 < n) out[base + 0] = excl;
    if (base + 1 < n) out[base + 1] = excl + v0;
    if (base + 2 < n) out[base + 2] = excl + v0 + v1;
    if (base + 3 < n) out[base + 3] = excl + v0 + v1 + v2;
}

__global__ void scan2_kernel(int nb) {
    __shared__ int s[512];
    int t = threadIdx.x;
    int v = (t < nb) ? g_bsums[t] : 0;
    s[t] = v;
    __syncthreads();
    for (int o = 1; o < 512; o <<= 1) {
        int x = (t >= o) ? s[t - o] : 0;
        __syncthreads();
        s[t] += x;
        __syncthreads();
    }
    if (t < nb) g_bsums[t] = s[t] - v;   // exclusive
}

__global__ void scan3_kernel(int* __restrict__ off, int* __restrict__ cur, int n) {
    int i = blockIdx.x * blockDim.x + threadIdx.x;
    if (i >= n) return;
    int o = off[i] + g_bsums[i >> 10];
    off[i] = o;
    cur[i] = o;
}

__global__ void fill_kernel(const int* __restrict__ ei, const int* __restrict__ et) {
    int e = blockIdx.x * blockDim.x + threadIdx.x;
    if (e >= E_EDGES) return;
    int key = ei[E_EDGES + e] * NUM_REL + et[e];
    int p = atomicAdd(&g_cur[key], 1);
    g_srcs[p] = ei[e];
}

// ---------------------------------------------------------------------------
// Gather-reduce aggregation (one warp per (node, rel) key) → packed mean into
// g_A[n, (1+r)*DIN : (2+r)*DIN].
// ---------------------------------------------------------------------------
template <int DIN>
__global__ void gather_agg_kernel(const float* __restrict__ feat) {
    const int K = DIN * (NUM_REL + 1);
    int w = (blockIdx.x * blockDim.x + threadIdx.x) >> 5;
    int lane = threadIdx.x & 31;
    if (w >= NKEYS) return;
    int n = w >> 3;
    int r = w & 7;
    int off = g_off[w];
    int cnt = g_deg[w];

    float4 a0 = make_float4(0.f, 0.f, 0.f, 0.f);
    float4 a1 = make_float4(0.f, 0.f, 0.f, 0.f);

    int i = 0;
    for (; i + 2 <= cnt; i += 2) {
        int s0 = g_srcs[off + i];
        int s1 = g_srcs[off + i + 1];
        const float4* p0 = (const float4*)(feat + (size_t)s0 * DIN) + lane;
        const float4* p1 = (const float4*)(feat + (size_t)s1 * DIN) + lane;
        float4 v0 = __ldg(p0);
        float4 v1 = __ldg(p1);
        float4 u0, u1;
        if (DIN == 256) { u0 = __ldg(p0 + 32); u1 = __ldg(p1 + 32); }
        a0.x += v0.x + v1.x; a0.y += v0.y + v1.y;
        a0.z += v0.z + v1.z; a0.w += v0.w + v1.w;
        if (DIN == 256) {
            a1.x += u0.x + u1.x; a1.y += u0.y + u1.y;
            a1.z += u0.z + u1.z; a1.w += u0.w + u1.w;
        }
    }
    if (i < cnt) {
        int s0 = g_srcs[off + i];
        const float4* p0 = (const float4*)(feat + (size_t)s0 * DIN) + lane;
        float4 v0 = __ldg(p0);
        a0.x += v0.x; a0.y += v0.y; a0.z += v0.z; a0.w += v0.w;
        if (DIN == 256) {
            float4 u0 = __ldg(p0 + 32);
            a1.x += u0.x; a1.y += u0.y; a1.z += u0.z; a1.w += u0.w;
        }
    }

    float sc = 1.0f / fmaxf((float)cnt, 1.0f);
    uint4 o0;
    o0.x = bf16_split_pack(a0.x * sc);
    o0.y = bf16_split_pack(a0.y * sc);
    o0.z = bf16_split_pack(a0.z * sc);
    o0.w = bf16_split_pack(a0.w * sc);
    uint4* dst = (uint4*)(g_A + (size_t)n * K + (1 + r) * DIN) + lane;
    *dst = o0;
    if (DIN == 256) {
        uint4 o1;
        o1.x = bf16_split_pack(a1.x * sc);
        o1.y = bf16_split_pack(a1.y * sc);
        o1.z = bf16_split_pack(a1.z * sc);
        o1.w = bf16_split_pack(a1.w * sc);
        *(dst + 32) = o1;
    }
}

// Layer-1 root copy: x packed into A[:, 0:128] (stride 1152)
__global__ void copy_feat1_kernel(const float* __restrict__ feat) {
    const int K = 1152;
    const int L = IN_DIM / 4;
    int idx = blockIdx.x * blockDim.x + threadIdx.x;
    if (idx >= N_NODES * L) return;
    int n = idx / L;
    int j = idx % L;
    float4 v = *((const float4*)(feat + (size_t)n * IN_DIM) + j);
    uint4 o;
    o.x = bf16_split_pack(v.x);
    o.y = bf16_split_pack(v.y);
    o.z = bf16_split_pack(v.z);
    o.w = bf16_split_pack(v.w);
    *((uint4*)(g_A + (size_t)n * K) + j) = o;
}

// ---------------------------------------------------------------------------
// Weight builders ([k][n] packed), each to its own buffer
// ---------------------------------------------------------------------------
__global__ void build_B_kernel(const float* __restrict__ root,
                               const float* __restrict__ W, int Kin,
                               uint32_t* __restrict__ out) {
    int total = Kin * (NUM_REL + 1) * HID;
    int idx = blockIdx.x * blockDim.x + threadIdx.x;
    if (idx >= total) return;
    int rootN = Kin * HID;
    float v = (idx < rootN) ? root[idx] : W[idx - rootN];
    out[idx] = bf16_split_pack(v);
}

// Decoder B' (256 x 512): cols 0..255 = mw1_top, 256..511 = mw1_bot
__global__ void build_Bdec_kernel(const float* __restrict__ mw1) {
    int idx = blockIdx.x * blockDim.x + threadIdx.x;   // 256*512
    if (idx >= HID * 2 * HID) return;
    int k = idx >> 9;
    int n = idx & 511;
    float v = (n < HID) ? mw1[k * HID + n] : mw1[(HID + k) * HID + (n - HID)];
    g_Bd[idx] = bf16_split_pack(v);
}

__global__ void pack_w2_kernel(const float* __restrict__ mw2) {
    int idx = blockIdx.x * blockDim.x + threadIdx.x;
    if (idx >= HID * (HID / 2)) return;
    g_Bw2[idx] = bf16_split_pack(mw2[idx]);
}

// ---------------------------------------------------------------------------
// Packed-split BF16 GEMM, 3-term compensation, cp.async 2-stage pipeline (R6).
// ---------------------------------------------------------------------------
#define ASTRIDE 20
#define BSTRIDE 132

__device__ __forceinline__ void cp16(uint32_t smem, const void* g) {
    asm volatile("cp.async.cg.shared.global [%0], [%1], 16;" :: "r"(smem), "l"(g));
}

#define MMA_BF16(d, a, b)                                                     \
    asm volatile("mma.sync.aligned.m16n8k16.row.col.f32.bf16.bf16.f32 "       \
                 "{%0,%1,%2,%3}, {%4,%5,%6,%7}, {%8,%9}, {%0,%1,%2,%3};"      \
                 : "+f"(d[0]), "+f"(d[1]), "+f"(d[2]), "+f"(d[3])             \
                 : "r"(a[0]), "r"(a[1]), "r"(a[2]), "r"(a[3]),                \
                   "r"(b[0]), "r"(b[1]))

__global__ __launch_bounds__(256, 2)
void gemm_ps_kernel(const uint32_t* __restrict__ A, const uint32_t* __restrict__ B,
                    float* __restrict__ C, const float* __restrict__ bias,
                    int M, int N, int K, int act) {
    __shared__ uint32_t As[2][128 * ASTRIDE];
    __shared__ uint32_t Bs[2][16 * BSTRIDE];

    const int tid  = threadIdx.x;
    const int warp = tid >> 5, lane = tid & 31;
    const int gid  = lane >> 2, tig = lane & 3;
    const int wm   = (warp & 1) * 64, wn = (warp >> 1) * 32;
    const int brow = blockIdx.y * 128, bcol = blockIdx.x * 128;

    float acc[4][4][4];
#pragma unroll
    for (int i = 0; i < 4; i++)
#pragma unroll
        for (int j = 0; j < 4; j++)
#pragma unroll
            for (int c = 0; c < 4; c++) acc[i][j][c] = 0.f;

    const int ar = tid >> 1;
    const int ac = (tid & 1) * 8;
    const int br = tid >> 4;
    const int bc = (tid & 15) * 8;

    const int arow_g = min(brow + ar, M - 1);
    const uint32_t* ag = A + (size_t)arow_g * K + ac;
    const uint32_t* bg = B + (size_t)br * N + bcol + bc;

    const uint32_t a_sm0 = (uint32_t)__cvta_generic_to_shared(&As[0][ar * ASTRIDE + ac]);
    const uint32_t a_sm1 = (uint32_t)__cvta_generic_to_shared(&As[1][ar * ASTRIDE + ac]);
    const uint32_t b_sm0 = (uint32_t)__cvta_generic_to_shared(&Bs[0][br * BSTRIDE + bc]);
    const uint32_t b_sm1 = (uint32_t)__cvta_generic_to_shared(&Bs[1][br * BSTRIDE + bc]);

    const int ntiles = K >> 4;

    cp16(a_sm0,      ag);
    cp16(a_sm0 + 16, ag + 4);
    cp16(b_sm0,      bg);
    cp16(b_sm0 + 16, bg + 4);
    asm volatile("cp.async.commit_group;");

    for (int t = 0; t < ntiles; t++) {
        if (t + 1 < ntiles) {
            int k0 = (t + 1) << 4;
            uint32_t asm_ = ((t + 1) & 1) ? a_sm1 : a_sm0;
            uint32_t bsm_ = ((t + 1) & 1) ? b_sm1 : b_sm0;
            cp16(asm_,      ag + k0);
            cp16(asm_ + 16, ag + k0 + 4);
            cp16(bsm_,      bg + (size_t)k0 * N);
            cp16(bsm_ + 16, bg + (size_t)k0 * N + 4);
            asm volatile("cp.async.commit_group;");
            asm volatile("cp.async.wait_group 1;");
        } else {
            asm volatile("cp.async.wait_group 0;");
        }
        __syncthreads();

        const uint32_t* as = As[t & 1];
        const uint32_t* bs = Bs[t & 1];

        uint32_t bh[4][2], bl[4][2];
#pragma unroll
        for (int nt = 0; nt < 4; nt++) {
            int n = wn + nt * 8 + gid;
            uint32_t r0 = bs[(tig * 2 + 0) * BSTRIDE + n];
            uint32_t r1 = bs[(tig * 2 + 1) * BSTRIDE + n];
            uint32_t r2 = bs[(tig * 2 + 8) * BSTRIDE + n];
            uint32_t r3 = bs[(tig * 2 + 9) * BSTRIDE + n];
            bh[nt][0] = __byte_perm(r0, r1, 0x5410);
            bh[nt][1] = __byte_perm(r2, r3, 0x5410);
            bl[nt][0] = __byte_perm(r0, r1, 0x7632);
            bl[nt][1] = __byte_perm(r2, r3, 0x7632);
        }
#pragma unroll
        for (int mt = 0; mt < 4; mt++) {
            int m0 = wm + mt * 16 + gid;
            uint2 p0 = *(const uint2*)&as[m0 * ASTRIDE + tig * 2];
            uint2 p1 = *(const uint2*)&as[(m0 + 8) * ASTRIDE + tig * 2];
            uint2 p2 = *(const uint2*)&as[m0 * ASTRIDE + tig * 2 + 8];
            uint2 p3 = *(const uint2*)&as[(m0 + 8) * ASTRIDE + tig * 2 + 8];
            uint32_t ah[4] = {__byte_perm(p0.x, p0.y, 0x5410), __byte_perm(p1.x, p1.y, 0x5410),
                              __byte_perm(p2.x, p2.y, 0x5410), __byte_perm(p3.x, p3.y, 0x5410)};
            uint32_t al[4] = {__byte_perm(p0.x, p0.y, 0x7632), __byte_perm(p1.x, p1.y, 0x7632),
                              __byte_perm(p2.x, p2.y, 0x7632), __byte_perm(p3.x, p3.y, 0x7632)};
#pragma unroll
            for (int nt = 0; nt < 4; nt++) {
                MMA_BF16(acc[mt][nt], ah, bh[nt]);
                MMA_BF16(acc[mt][nt], ah, bl[nt]);
                MMA_BF16(acc[mt][nt], al, bh[nt]);
            }
        }
        __syncthreads();
    }

#pragma unroll
    for (int mt = 0; mt < 4; mt++) {
        int r0 = brow + wm + mt * 16 + gid;
#pragma unroll
        for (int nt = 0; nt < 4; nt++) {
            int c = bcol + wn + nt * 8 + 2 * tig;
            float bb0 = bias ? bias[c] : 0.f;
            float bb1 = bias ? bias[c + 1] : 0.f;
            float v0 = acc[mt][nt][0] + bb0;
            float v1 = acc[mt][nt][1] + bb1;
            float v2 = acc[mt][nt][2] + bb0;
            float v3 = acc[mt][nt][3] + bb1;
            if (act == 1) {
                const float is2 = 0.70710678118654752f;
                v0 = 0.5f * v0 * (1.0f + erff(v0 * is2));
                v1 = 0.5f * v1 * (1.0f + erff(v1 * is2));
                v2 = 0.5f * v2 * (1.0f + erff(v2 * is2));
                v3 = 0.5f * v3 * (1.0f + erff(v3 * is2));
            }
            if (r0 < M)
                *(float2*)(C + (size_t)r0 * N + c) = make_float2(v0, v1);
            if (r0 + 8 < M)
                *(float2*)(C + (size_t)(r0 + 8) * N + c) = make_float2(v2, v3);
        }
    }
}

// ---------------------------------------------------------------------------
// Layer 1: ReLU + LN → fp32 h1 AND packed A-root (stride 2304) [fuses copy_feat2]
// ---------------------------------------------------------------------------
__global__ void relu_ln1_kernel(const float* __restrict__ hp,
                                const float* __restrict__ g,
                                const float* __restrict__ b,
                                float* __restrict__ out) {
    int row = blockIdx.x;
    int tid = threadIdx.x;   // 256 == HID
    float v = fmaxf(hp[(size_t)row * HID + tid], 0.0f);

    __shared__ float red[8];
    __shared__ float s_mu, s_rs;

    float s = v;
#pragma unroll
    for (int o = 16; o; o >>= 1) s += __shfl_xor_sync(0xFFFFFFFFu, s, o);
    if ((tid & 31) == 0) red[tid >> 5] = s;
    __syncthreads();
    if (tid == 0) {
        float t = 0.f;
#pragma unroll
        for (int i = 0; i < 8; i++) t += red[i];
        s_mu = t / (float)HID;
    }
    __syncthreads();

    float d = v - s_mu;
    float s2 = d * d;
#pragma unroll
    for (int o = 16; o; o >>= 1) s2 += __shfl_xor_sync(0xFFFFFFFFu, s2, o);
    if ((tid & 31) == 0) red[tid >> 5] = s2;
    __syncthreads();
    if (tid == 0) {
        float t = 0.f;
#pragma unroll
        for (int i = 0; i < 8; i++) t += red[i];
        s_rs = rsqrtf(t / (float)HID + 1e-5f);
    }
    __syncthreads();

    float o = d * s_rs * g[tid] + b[tid];
    out[(size_t)row * HID + tid] = o;                       // fp32 h1 (dense)
    g_A[(size_t)row * 2304 + tid] = bf16_split_pack(o);     // packed A root
}

// Layer 2 variant: packed(resid + LN(relu(hp)))
__global__ void relu_ln_pack_kernel(const float* __restrict__ hp,
                                    const float* __restrict__ g,
                                    const float* __restrict__ b,
                                    uint32_t* __restrict__ outp,
                                    const float* __restrict__ resid) {
    int row = blockIdx.x;
    int tid = threadIdx.x;
    float v = fmaxf(hp[(size_t)row * HID + tid], 0.0f);

    __shared__ float red[8];
    __shared__ float s_mu, s_rs;

    float s = v;
#pragma unroll
    for (int o = 16; o; o >>= 1) s += __shfl_xor_sync(0xFFFFFFFFu, s, o);
    if ((tid & 31) == 0) red[tid >> 5] = s;
    __syncthreads();
    if (tid == 0) {
        float t = 0.f;
#pragma unroll
        for (int i = 0; i < 8; i++) t += red[i];
        s_mu = t / (float)HID;
    }
    __syncthreads();

    float d = v - s_mu;
    float s2 = d * d;
#pragma unroll
    for (int o = 16; o; o >>= 1) s2 += __shfl_xor_sync(0xFFFFFFFFu, s2, o);
    if ((tid & 31) == 0) red[tid >> 5] = s2;
    __syncthreads();
    if (tid == 0) {
        float t = 0.f;
#pragma unroll
        for (int i = 0; i < 8; i++) t += red[i];
        s_rs = rsqrtf(t / (float)HID + 1e-5f);
    }
    __syncthreads();

    float o = d * s_rs * g[tid] + b[tid] + resid[(size_t)row * HID + tid];
    outp[(size_t)row * HID + tid] = bf16_split_pack(o);
}

// ---------------------------------------------------------------------------
// Fused decoder stage 1: Z1[m,c] = packed(gelu(P[u][c] + P[v][256+c] + b1[c]))
// ---------------------------------------------------------------------------
__global__ void decode_fuse_kernel(const int* __restrict__ dec,
                                   const float* __restrict__ b1) {
    int idx = blockIdx.x * blockDim.x + threadIdx.x;
    if (idx >= M_DEC * (HID / 4)) return;
    int m = idx >> 6;
    int j = idx & 63;
    int u = dec[m * 2 + 0];
    int v = dec[m * 2 + 1];
    float4 p = __ldg((const float4*)(g_P + (size_t)u * 512) + j);
    float4 q = __ldg((const float4*)(g_P + (size_t)v * 512 + 256) + j);
    float4 bb = *((const float4*)b1 + j);
    const float is2 = 0.70710678118654752f;
    float zx = p.x + q.x + bb.x; zx = 0.5f * zx * (1.0f + erff(zx * is2));
    float zy = p.y + q.y + bb.y; zy = 0.5f * zy * (1.0f + erff(zy * is2));
    float zz = p.z + q.z + bb.z; zz = 0.5f * zz * (1.0f + erff(zz * is2));
    float zw = p.w + q.w + bb.w; zw = 0.5f * zw * (1.0f + erff(zw * is2));
    uint4 o;
    o.x = bf16_split_pack(zx);
    o.y = bf16_split_pack(zy);
    o.z = bf16_split_pack(zz);
    o.w = bf16_split_pack(zw);
    *((uint4*)(g_Z1 + (size_t)m * HID) + j) = o;
}

// ---------------------------------------------------------------------------
__global__ void final_kernel(const float* __restrict__ w3,
                             const float* __restrict__ b3,
                             float* __restrict__ out) {
    long long t = (long long)blockIdx.x * blockDim.x + threadIdx.x;
    int m = (int)(t >> 5);
    int lane = (int)(t & 31);
    if (m >= M_DEC) return;
    float4 z = *(const float4*)(g_Z2 + (size_t)m * 128 + lane * 4);
    const float* w = w3 + lane * 4 * 2;
    float s0 = z.x * w[0] + z.y * w[2] + z.z * w[4] + z.w * w[6];
    float s1 = z.x * w[1] + z.y * w[3] + z.z * w[5] + z.w * w[7];
#pragma unroll
    for (int o = 16; o; o >>= 1) {
        s0 += __shfl_xor_sync(0xFFFFFFFFu, s0, o);
        s1 += __shfl_xor_sync(0xFFFFFFFFu, s1, o);
    }
    if (lane == 0) {
        out[m * 2 + 0] = s0 + b3[0];
        out[m * 2 + 1] = s1 + b3[1];
    }
}

// ---------------------------------------------------------------------------
static inline int blocks_for(long long n, int bs) { return (int)((n + bs - 1) / bs); }

extern "C" void kernel_launch(void* const* d_in, const int* in_sizes, int n_in,
                              void* d_out, int out_size) {
    const float* x     = (const float*)d_in[0];
    const int*   ei    = (const int*)  d_in[1];
    const int*   et    = (const int*)  d_in[2];
    const int*   dec   = (const int*)  d_in[3];
    const float* W1    = (const float*)d_in[4];
    const float* root1 = (const float*)d_in[5];
    const float* b1    = (const float*)d_in[6];
    const float* W2    = (const float*)d_in[7];
    const float* root2 = (const float*)d_in[8];
    const float* b2    = (const float*)d_in[9];
    const float* ln1g  = (const float*)d_in[10];
    const float* ln1b  = (const float*)d_in[11];
    const float* ln2g  = (const float*)d_in[12];
    const float* ln2b  = (const float*)d_in[13];
    const float* mw1   = (const float*)d_in[14];
    const float* mb1   = (const float*)d_in[15];
    const float* mw2   = (const float*)d_in[16];
    const float* mb2   = (const float*)d_in[17];
    const float* mw3   = (const float*)d_in[18];
    const float* mb3   = (const float*)d_in[19];
    float* out = (float*)d_out;

    uint32_t *A, *B1p, *B2p, *Bd, *Bw2, *hP, *Z1;
    float *hp, *h1, *P, *Z2;
    int *deg, *off, *cur;
    cudaGetSymbolAddress((void**)&A,   g_A);
    cudaGetSymbolAddress((void**)&B1p, g_B1);
    cudaGetSymbolAddress((void**)&B2p, g_B2);
    cudaGetSymbolAddress((void**)&Bd,  g_Bd);
    cudaGetSymbolAddress((void**)&Bw2, g_Bw2);
    cudaGetSymbolAddress((void**)&hP,  g_hP);
    cudaGetSymbolAddress((void**)&Z1,  g_Z1);
    cudaGetSymbolAddress((void**)&hp,  g_hp);
    cudaGetSymbolAddress((void**)&h1,  g_h1);
    cudaGetSymbolAddress((void**)&P,   g_P);
    cudaGetSymbolAddress((void**)&Z2,  g_Z2);
    cudaGetSymbolAddress((void**)&deg, g_deg);
    cudaGetSymbolAddress((void**)&off, g_off);
    cudaGetSymbolAddress((void**)&cur, g_cur);

    // ===================== CSR build =====================
    zero_int_kernel<<<blocks_for(NKEYS / 4, 256), 256>>>(deg, NKEYS / 4);
    hist_kernel<<<blocks_for(E_EDGES, 256), 256>>>(ei, et);
    int nblk = (NKEYS + 1023) / 1024;
    scan1_kernel<<<nblk, 256>>>(deg, off, NKEYS);
    scan2_kernel<<<1, 512>>>(nblk);
    scan3_kernel<<<blocks_for(NKEYS, 256), 256>>>(off, cur, NKEYS);
    fill_kernel<<<blocks_for(E_EDGES, 256), 256>>>(ei, et);

    // ===================== Weight packs + layer-1 root =====================
    copy_feat1_kernel<<<blocks_for(N_NODES * (IN_DIM / 4), 256), 256>>>(x);
    build_B_kernel<<<blocks_for(1152 * HID, 256), 256>>>(root1, W1, IN_DIM, B1p);
    build_B_kernel<<<blocks_for(2304 * HID, 256), 256>>>(root2, W2, HID, B2p);
    build_Bdec_kernel<<<blocks_for(2 * HID * HID, 256), 256>>>(mw1);
    pack_w2_kernel<<<blocks_for(HID * (HID / 2), 256), 256>>>(mw2);

    // ===================== Layer 1 (K = 1152) =====================
    gather_agg_kernel<IN_DIM><<<blocks_for((long long)NKEYS * 32, 256), 256>>>(x);
    {
        dim3 grid(HID / 128, (N_NODES + 127) / 128);
        gemm_ps_kernel<<<grid, 256>>>(A, B1p, hp, b1, N_NODES, HID, 1152, 0);
    }
    relu_ln1_kernel<<<N_NODES, HID>>>(hp, ln1g, ln1b, h1);   // also packs A root

    // ===================== Layer 2 (K = 2304) =====================
    gather_agg_kernel<HID><<<blocks_for((long long)NKEYS * 32, 256), 256>>>(h1);
    {
        dim3 grid(HID / 128, (N_NODES + 127) / 128);
        gemm_ps_kernel<<<grid, 256>>>(A, B2p, hp, b2, N_NODES, HID, 2304, 0);
    }
    relu_ln_pack_kernel<<<N_NODES, HID>>>(hp, ln2g, ln2b, hP, h1);

    // ===================== Decoder =====================
    {
        dim3 gp(4, (N_NODES + 127) / 128);
        gemm_ps_kernel<<<gp, 256>>>(hP, Bd, P, nullptr, N_NODES, 2 * HID, HID, 0);

        decode_fuse_kernel<<<blocks_for((long long)M_DEC * (HID / 4), 256), 256>>>(dec, mb1);

        dim3 g2(1, (M_DEC + 127) / 128);
        gemm_ps_kernel<<<g2, 256>>>(Z1, Bw2, Z2, mb2, M_DEC, HID / 2, HID, 1);

        final_kernel<<<blocks_for((long long)M_DEC * 32, 256), 256>>>(mw3, mb3, out);
    }
}

// round 15
// speedup vs baseline: 1.2001x; 1.0206x over previous
#include <cuda_runtime.h>
#include <cuda_bf16.h>
#include <cstdint>
#include <cstddef>

#define N_NODES 50000
#define NUM_REL 8
#define IN_DIM  128
#define HID     256
#define E_EDGES 1600000
#define M_DEC   200000
#define NKEYS   (N_NODES * NUM_REL)      // 400000

// ---------------------------------------------------------------------------
// Device scratch. Packed format ("ps32"): one uint32 per element =
// (bf16(lo) << 16) | bf16(hi), hi = bf16(x), lo = bf16(x - float(hi)).
// ---------------------------------------------------------------------------
__device__ int      g_deg[NKEYS];
__device__ int      g_off[NKEYS];
__device__ int      g_cur[NKEYS];
__device__ int      g_srcs[E_EDGES];
__device__ int      g_bsums[512];
__device__ uint32_t g_A[(size_t)N_NODES * (HID + NUM_REL * HID)];   // packed, N x 2304 (layer1: N x 1152)
__device__ uint32_t g_B1[1152 * HID];            // layer1 weights [k][n] packed
__device__ uint32_t g_B2[2304 * HID];            // layer2 weights [k][n] packed
__device__ uint32_t g_Bd[HID * 2 * HID];         // decoder W1' (256 x 512) packed
__device__ uint32_t g_Bw2[HID * (HID / 2)];      // decoder W2  (256 x 128) packed
__device__ float    g_hp[(size_t)N_NODES * HID];
__device__ float    g_h1[(size_t)N_NODES * HID];                    // fp32 h1 (dense, L2-hot)
__device__ uint32_t g_hP[(size_t)N_NODES * HID];                    // packed final h
__device__ float    g_P [(size_t)N_NODES * 2 * HID];                // 50000 x 512
__device__ uint32_t g_Z1[(size_t)M_DEC * HID];                      // packed

// ---------------------------------------------------------------------------
__device__ __forceinline__ uint32_t bf16_split_pack(float x) {
    __nv_bfloat16 h = __float2bfloat16(x);
    float hf = __bfloat162float(h);
    __nv_bfloat16 l = __float2bfloat16(x - hf);
    return ((uint32_t)__bfloat16_as_ushort(l) << 16) | (uint32_t)__bfloat16_as_ushort(h);
}

__global__ void zero_int_kernel(int* __restrict__ p, int n4) {
    int i = blockIdx.x * blockDim.x + threadIdx.x;
    if (i < n4) ((int4*)p)[i] = make_int4(0, 0, 0, 0);
}

// ---------------------------------------------------------------------------
// CSR build over keys (dst*8 + rel)
// ---------------------------------------------------------------------------
__global__ void hist_kernel(const int* __restrict__ ei, const int* __restrict__ et) {
    int e = blockIdx.x * blockDim.x + threadIdx.x;
    if (e >= E_EDGES) return;
    int key = ei[E_EDGES + e] * NUM_REL + et[e];
    atomicAdd(&g_deg[key], 1);
}

__global__ void scan1_kernel(const int* __restrict__ in, int* __restrict__ out, int n) {
    __shared__ int s[256];
    int t = threadIdx.x;
    int base = blockIdx.x * 1024 + t * 4;
    int v0 = 0, v1 = 0, v2 = 0, v3 = 0;
    if (base + 0 < n) v0 = in[base + 0];
    if (base + 1 < n) v1 = in[base + 1];
    if (base + 2 < n) v2 = in[base + 2];
    if (base + 3 < n) v3 = in[base + 3];
    int tsum = v0 + v1 + v2 + v3;
    s[t] = tsum;
    __syncthreads();
    for (int o = 1; o < 256; o <<= 1) {
        int x = (t >= o) ? s[t - o] : 0;
        __syncthreads();
        s[t] += x;
        __syncthreads();
    }
    int excl = s[t] - tsum;
    if (t == 255) g_bsums[blockIdx.x] = s[255];
    if (base + 0 < n) out[base + 0] = excl;
    if (base + 1 < n) out[base + 1] = excl + v0;
    if (base + 2 < n) out[base + 2] = excl + v0 + v1;
    if (base + 3 < n) out[base + 3] = excl + v0 + v1 + v2;
}

__global__ void scan2_kernel(int nb) {
    __shared__ int s[512];
    int t = threadIdx.x;
    int v = (t < nb) ? g_bsums[t] : 0;
    s[t] = v;
    __syncthreads();
    for (int o = 1; o < 512; o <<= 1) {
        int x = (t >= o) ? s[t - o] : 0;
        __syncthreads();
        s[t] += x;
        __syncthreads();
    }
    if (t < nb) g_bsums[t] = s[t] - v;   // exclusive
}

__global__ void scan3_kernel(int* __restrict__ off, int* __restrict__ cur, int n) {
    int i = blockIdx.x * blockDim.x + threadIdx.x;
    if (i >= n) return;
    int o = off[i] + g_bsums[i >> 10];
    off[i] = o;
    cur[i] = o;
}

__global__ void fill_kernel(const int* __restrict__ ei, const int* __restrict__ et) {
    int e = blockIdx.x * blockDim.x + threadIdx.x;
    if (e >= E_EDGES) return;
    int key = ei[E_EDGES + e] * NUM_REL + et[e];
    int p = atomicAdd(&g_cur[key], 1);
    g_srcs[p] = ei[e];
}

// ---------------------------------------------------------------------------
// Gather-reduce aggregation (one warp per (node, rel) key) → packed mean into
// g_A[n, (1+r)*DIN : (2+r)*DIN].  fp32 inputs (precision floor: ps32 or fp32).
// ---------------------------------------------------------------------------
template <int DIN>
__global__ void gather_agg_kernel(const float* __restrict__ feat) {
    const int K = DIN * (NUM_REL + 1);
    int w = (blockIdx.x * blockDim.x + threadIdx.x) >> 5;
    int lane = threadIdx.x & 31;
    if (w >= NKEYS) return;
    int n = w >> 3;
    int r = w & 7;
    int off = g_off[w];
    int cnt = g_deg[w];

    float4 a0 = make_float4(0.f, 0.f, 0.f, 0.f);
    float4 a1 = make_float4(0.f, 0.f, 0.f, 0.f);

    int i = 0;
    for (; i + 2 <= cnt; i += 2) {
        int s0 = g_srcs[off + i];
        int s1 = g_srcs[off + i + 1];
        const float4* p0 = (const float4*)(feat + (size_t)s0 * DIN) + lane;
        const float4* p1 = (const float4*)(feat + (size_t)s1 * DIN) + lane;
        float4 v0 = __ldg(p0);
        float4 v1 = __ldg(p1);
        float4 u0, u1;
        if (DIN == 256) { u0 = __ldg(p0 + 32); u1 = __ldg(p1 + 32); }
        a0.x += v0.x + v1.x; a0.y += v0.y + v1.y;
        a0.z += v0.z + v1.z; a0.w += v0.w + v1.w;
        if (DIN == 256) {
            a1.x += u0.x + u1.x; a1.y += u0.y + u1.y;
            a1.z += u0.z + u1.z; a1.w += u0.w + u1.w;
        }
    }
    if (i < cnt) {
        int s0 = g_srcs[off + i];
        const float4* p0 = (const float4*)(feat + (size_t)s0 * DIN) + lane;
        float4 v0 = __ldg(p0);
        a0.x += v0.x; a0.y += v0.y; a0.z += v0.z; a0.w += v0.w;
        if (DIN == 256) {
            float4 u0 = __ldg(p0 + 32);
            a1.x += u0.x; a1.y += u0.y; a1.z += u0.z; a1.w += u0.w;
        }
    }

    float sc = 1.0f / fmaxf((float)cnt, 1.0f);
    uint4 o0;
    o0.x = bf16_split_pack(a0.x * sc);
    o0.y = bf16_split_pack(a0.y * sc);
    o0.z = bf16_split_pack(a0.z * sc);
    o0.w = bf16_split_pack(a0.w * sc);
    uint4* dst = (uint4*)(g_A + (size_t)n * K + (1 + r) * DIN) + lane;
    *dst = o0;
    if (DIN == 256) {
        uint4 o1;
        o1.x = bf16_split_pack(a1.x * sc);
        o1.y = bf16_split_pack(a1.y * sc);
        o1.z = bf16_split_pack(a1.z * sc);
        o1.w = bf16_split_pack(a1.w * sc);
        *(dst + 32) = o1;
    }
}

// Layer-1 root copy: x packed into A[:, 0:128] (stride 1152)
__global__ void copy_feat1_kernel(const float* __restrict__ feat) {
    const int K = 1152;
    const int L = IN_DIM / 4;
    int idx = blockIdx.x * blockDim.x + threadIdx.x;
    if (idx >= N_NODES * L) return;
    int n = idx / L;
    int j = idx % L;
    float4 v = *((const float4*)(feat + (size_t)n * IN_DIM) + j);
    uint4 o;
    o.x = bf16_split_pack(v.x);
    o.y = bf16_split_pack(v.y);
    o.z = bf16_split_pack(v.z);
    o.w = bf16_split_pack(v.w);
    *((uint4*)(g_A + (size_t)n * K) + j) = o;
}

// ---------------------------------------------------------------------------
// Weight builders ([k][n] packed), each to its own buffer
// ---------------------------------------------------------------------------
__global__ void build_B_kernel(const float* __restrict__ root,
                               const float* __restrict__ W, int Kin,
                               uint32_t* __restrict__ out) {
    int total = Kin * (NUM_REL + 1) * HID;
    int idx = blockIdx.x * blockDim.x + threadIdx.x;
    if (idx >= total) return;
    int rootN = Kin * HID;
    float v = (idx < rootN) ? root[idx] : W[idx - rootN];
    out[idx] = bf16_split_pack(v);
}

// Decoder B' (256 x 512): cols 0..255 = mw1_top, 256..511 = mw1_bot
__global__ void build_Bdec_kernel(const float* __restrict__ mw1) {
    int idx = blockIdx.x * blockDim.x + threadIdx.x;   // 256*512
    if (idx >= HID * 2 * HID) return;
    int k = idx >> 9;
    int n = idx & 511;
    float v = (n < HID) ? mw1[k * HID + n] : mw1[(HID + k) * HID + (n - HID)];
    g_Bd[idx] = bf16_split_pack(v);
}

__global__ void pack_w2_kernel(const float* __restrict__ mw2) {
    int idx = blockIdx.x * blockDim.x + threadIdx.x;
    if (idx >= HID * (HID / 2)) return;
    g_Bw2[idx] = bf16_split_pack(mw2[idx]);
}

// ---------------------------------------------------------------------------
// Packed-split BF16 GEMM, 3-term compensation, cp.async 2-stage pipeline (R6).
// ---------------------------------------------------------------------------
#define ASTRIDE 20
#define BSTRIDE 132

__device__ __forceinline__ void cp16(uint32_t smem, const void* g) {
    asm volatile("cp.async.cg.shared.global [%0], [%1], 16;" :: "r"(smem), "l"(g));
}

#define MMA_BF16(d, a, b)                                                     \
    asm volatile("mma.sync.aligned.m16n8k16.row.col.f32.bf16.bf16.f32 "       \
                 "{%0,%1,%2,%3}, {%4,%5,%6,%7}, {%8,%9}, {%0,%1,%2,%3};"      \
                 : "+f"(d[0]), "+f"(d[1]), "+f"(d[2]), "+f"(d[3])             \
                 : "r"(a[0]), "r"(a[1]), "r"(a[2]), "r"(a[3]),                \
                   "r"(b[0]), "r"(b[1]))

__global__ __launch_bounds__(256, 2)
void gemm_ps_kernel(const uint32_t* __restrict__ A, const uint32_t* __restrict__ B,
                    float* __restrict__ C, const float* __restrict__ bias,
                    int M, int N, int K, int act) {
    __shared__ uint32_t As[2][128 * ASTRIDE];
    __shared__ uint32_t Bs[2][16 * BSTRIDE];

    const int tid  = threadIdx.x;
    const int warp = tid >> 5, lane = tid & 31;
    const int gid  = lane >> 2, tig = lane & 3;
    const int wm   = (warp & 1) * 64, wn = (warp >> 1) * 32;
    const int brow = blockIdx.y * 128, bcol = blockIdx.x * 128;

    float acc[4][4][4];
#pragma unroll
    for (int i = 0; i < 4; i++)
#pragma unroll
        for (int j = 0; j < 4; j++)
#pragma unroll
            for (int c = 0; c < 4; c++) acc[i][j][c] = 0.f;

    const int ar = tid >> 1;
    const int ac = (tid & 1) * 8;
    const int br = tid >> 4;
    const int bc = (tid & 15) * 8;

    const int arow_g = min(brow + ar, M - 1);
    const uint32_t* ag = A + (size_t)arow_g * K + ac;
    const uint32_t* bg = B + (size_t)br * N + bcol + bc;

    const uint32_t a_sm0 = (uint32_t)__cvta_generic_to_shared(&As[0][ar * ASTRIDE + ac]);
    const uint32_t a_sm1 = (uint32_t)__cvta_generic_to_shared(&As[1][ar * ASTRIDE + ac]);
    const uint32_t b_sm0 = (uint32_t)__cvta_generic_to_shared(&Bs[0][br * BSTRIDE + bc]);
    const uint32_t b_sm1 = (uint32_t)__cvta_generic_to_shared(&Bs[1][br * BSTRIDE + bc]);

    const int ntiles = K >> 4;

    cp16(a_sm0,      ag);
    cp16(a_sm0 + 16, ag + 4);
    cp16(b_sm0,      bg);
    cp16(b_sm0 + 16, bg + 4);
    asm volatile("cp.async.commit_group;");

    for (int t = 0; t < ntiles; t++) {
        if (t + 1 < ntiles) {
            int k0 = (t + 1) << 4;
            uint32_t asm_ = ((t + 1) & 1) ? a_sm1 : a_sm0;
            uint32_t bsm_ = ((t + 1) & 1) ? b_sm1 : b_sm0;
            cp16(asm_,      ag + k0);
            cp16(asm_ + 16, ag + k0 + 4);
            cp16(bsm_,      bg + (size_t)k0 * N);
            cp16(bsm_ + 16, bg + (size_t)k0 * N + 4);
            asm volatile("cp.async.commit_group;");
            asm volatile("cp.async.wait_group 1;");
        } else {
            asm volatile("cp.async.wait_group 0;");
        }
        __syncthreads();

        const uint32_t* as = As[t & 1];
        const uint32_t* bs = Bs[t & 1];

        uint32_t bh[4][2], bl[4][2];
#pragma unroll
        for (int nt = 0; nt < 4; nt++) {
            int n = wn + nt * 8 + gid;
            uint32_t r0 = bs[(tig * 2 + 0) * BSTRIDE + n];
            uint32_t r1 = bs[(tig * 2 + 1) * BSTRIDE + n];
            uint32_t r2 = bs[(tig * 2 + 8) * BSTRIDE + n];
            uint32_t r3 = bs[(tig * 2 + 9) * BSTRIDE + n];
            bh[nt][0] = __byte_perm(r0, r1, 0x5410);
            bh[nt][1] = __byte_perm(r2, r3, 0x5410);
            bl[nt][0] = __byte_perm(r0, r1, 0x7632);
            bl[nt][1] = __byte_perm(r2, r3, 0x7632);
        }
#pragma unroll
        for (int mt = 0; mt < 4; mt++) {
            int m0 = wm + mt * 16 + gid;
            uint2 p0 = *(const uint2*)&as[m0 * ASTRIDE + tig * 2];
            uint2 p1 = *(const uint2*)&as[(m0 + 8) * ASTRIDE + tig * 2];
            uint2 p2 = *(const uint2*)&as[m0 * ASTRIDE + tig * 2 + 8];
            uint2 p3 = *(const uint2*)&as[(m0 + 8) * ASTRIDE + tig * 2 + 8];
            uint32_t ah[4] = {__byte_perm(p0.x, p0.y, 0x5410), __byte_perm(p1.x, p1.y, 0x5410),
                              __byte_perm(p2.x, p2.y, 0x5410), __byte_perm(p3.x, p3.y, 0x5410)};
            uint32_t al[4] = {__byte_perm(p0.x, p0.y, 0x7632), __byte_perm(p1.x, p1.y, 0x7632),
                              __byte_perm(p2.x, p2.y, 0x7632), __byte_perm(p3.x, p3.y, 0x7632)};
#pragma unroll
            for (int nt = 0; nt < 4; nt++) {
                MMA_BF16(acc[mt][nt], ah, bh[nt]);
                MMA_BF16(acc[mt][nt], ah, bl[nt]);
                MMA_BF16(acc[mt][nt], al, bh[nt]);
            }
        }
        __syncthreads();
    }

#pragma unroll
    for (int mt = 0; mt < 4; mt++) {
        int r0 = brow + wm + mt * 16 + gid;
#pragma unroll
        for (int nt = 0; nt < 4; nt++) {
            int c = bcol + wn + nt * 8 + 2 * tig;
            float bb0 = bias ? bias[c] : 0.f;
            float bb1 = bias ? bias[c + 1] : 0.f;
            float v0 = acc[mt][nt][0] + bb0;
            float v1 = acc[mt][nt][1] + bb1;
            float v2 = acc[mt][nt][2] + bb0;
            float v3 = acc[mt][nt][3] + bb1;
            if (act == 1) {
                const float is2 = 0.70710678118654752f;
                v0 = 0.5f * v0 * (1.0f + erff(v0 * is2));
                v1 = 0.5f * v1 * (1.0f + erff(v1 * is2));
                v2 = 0.5f * v2 * (1.0f + erff(v2 * is2));
                v3 = 0.5f * v3 * (1.0f + erff(v3 * is2));
            }
            if (r0 < M)
                *(float2*)(C + (size_t)r0 * N + c) = make_float2(v0, v1);
            if (r0 + 8 < M)
                *(float2*)(C + (size_t)(r0 + 8) * N + c) = make_float2(v2, v3);
        }
    }
}

// ---------------------------------------------------------------------------
// Z2 GEMM with FUSED final projection:
//   out[m, 0:2] = gelu(Z1[m,:] @ W2 + b2) @ w3 + b3
// Same mainloop as gemm_ps (N=128, one column block per row band, so each CTA
// owns complete rows). Epilogue reduces the GELU'd tile against w3 via smem.
// ---------------------------------------------------------------------------
__global__ __launch_bounds__(256, 2)
void gemm_z2_final_kernel(const uint32_t* __restrict__ A, const uint32_t* __restrict__ B,
                          const float* __restrict__ bias,
                          const float* __restrict__ w3, const float* __restrict__ b3,
                          float* __restrict__ out, int M, int K) {
    const int N = 128;
    __shared__ uint32_t As[2][128 * ASTRIDE];
    __shared__ uint32_t Bs[2][16 * BSTRIDE];

    const int tid  = threadIdx.x;
    const int warp = tid >> 5, lane = tid & 31;
    const int gid  = lane >> 2, tig = lane & 3;
    const int wm   = (warp & 1) * 64, wn = (warp >> 1) * 32;
    const int brow = blockIdx.y * 128;

    float acc[4][4][4];
#pragma unroll
    for (int i = 0; i < 4; i++)
#pragma unroll
        for (int j = 0; j < 4; j++)
#pragma unroll
            for (int c = 0; c < 4; c++) acc[i][j][c] = 0.f;

    const int ar = tid >> 1;
    const int ac = (tid & 1) * 8;
    const int br = tid >> 4;
    const int bc = (tid & 15) * 8;

    const int arow_g = min(brow + ar, M - 1);
    const uint32_t* ag = A + (size_t)arow_g * K + ac;
    const uint32_t* bg = B + (size_t)br * N + bc;

    const uint32_t a_sm0 = (uint32_t)__cvta_generic_to_shared(&As[0][ar * ASTRIDE + ac]);
    const uint32_t a_sm1 = (uint32_t)__cvta_generic_to_shared(&As[1][ar * ASTRIDE + ac]);
    const uint32_t b_sm0 = (uint32_t)__cvta_generic_to_shared(&Bs[0][br * BSTRIDE + bc]);
    const uint32_t b_sm1 = (uint32_t)__cvta_generic_to_shared(&Bs[1][br * BSTRIDE + bc]);

    const int ntiles = K >> 4;

    cp16(a_sm0,      ag);
    cp16(a_sm0 + 16, ag + 4);
    cp16(b_sm0,      bg);
    cp16(b_sm0 + 16, bg + 4);
    asm volatile("cp.async.commit_group;");

    for (int t = 0; t < ntiles; t++) {
        if (t + 1 < ntiles) {
            int k0 = (t + 1) << 4;
            uint32_t asm_ = ((t + 1) & 1) ? a_sm1 : a_sm0;
            uint32_t bsm_ = ((t + 1) & 1) ? b_sm1 : b_sm0;
            cp16(asm_,      ag + k0);
            cp16(asm_ + 16, ag + k0 + 4);
            cp16(bsm_,      bg + (size_t)k0 * N);
            cp16(bsm_ + 16, bg + (size_t)k0 * N + 4);
            asm volatile("cp.async.commit_group;");
            asm volatile("cp.async.wait_group 1;");
        } else {
            asm volatile("cp.async.wait_group 0;");
        }
        __syncthreads();

        const uint32_t* as = As[t & 1];
        const uint32_t* bs = Bs[t & 1];

        uint32_t bh[4][2], bl[4][2];
#pragma unroll
        for (int nt = 0; nt < 4; nt++) {
            int n = wn + nt * 8 + gid;
            uint32_t r0 = bs[(tig * 2 + 0) * BSTRIDE + n];
            uint32_t r1 = bs[(tig * 2 + 1) * BSTRIDE + n];
            uint32_t r2 = bs[(tig * 2 + 8) * BSTRIDE + n];
            uint32_t r3 = bs[(tig * 2 + 9) * BSTRIDE + n];
            bh[nt][0] = __byte_perm(r0, r1, 0x5410);
            bh[nt][1] = __byte_perm(r2, r3, 0x5410);
            bl[nt][0] = __byte_perm(r0, r1, 0x7632);
            bl[nt][1] = __byte_perm(r2, r3, 0x7632);
        }
#pragma unroll
        for (int mt = 0; mt < 4; mt++) {
            int m0 = wm + mt * 16 + gid;
            uint2 p0 = *(const uint2*)&as[m0 * ASTRIDE + tig * 2];
            uint2 p1 = *(const uint2*)&as[(m0 + 8) * ASTRIDE + tig * 2];
            uint2 p2 = *(const uint2*)&as[m0 * ASTRIDE + tig * 2 + 8];
            uint2 p3 = *(const uint2*)&as[(m0 + 8) * ASTRIDE + tig * 2 + 8];
            uint32_t ah[4] = {__byte_perm(p0.x, p0.y, 0x5410), __byte_perm(p1.x, p1.y, 0x5410),
                              __byte_perm(p2.x, p2.y, 0x5410), __byte_perm(p3.x, p3.y, 0x5410)};
            uint32_t al[4] = {__byte_perm(p0.x, p0.y, 0x7632), __byte_perm(p1.x, p1.y, 0x7632),
                              __byte_perm(p2.x, p2.y, 0x7632), __byte_perm(p3.x, p3.y, 0x7632)};
#pragma unroll
            for (int nt = 0; nt < 4; nt++) {
                MMA_BF16(acc[mt][nt], ah, bh[nt]);
                MMA_BF16(acc[mt][nt], ah, bl[nt]);
                MMA_BF16(acc[mt][nt], al, bh[nt]);
            }
        }
        __syncthreads();
    }

    // ---- fused epilogue: gelu + 128->2 projection ----
    float* sums = (float*)As;          // reuse A-stage smem (256 floats needed)
    sums[tid] = 0.f;
    __syncthreads();

    const float is2 = 0.70710678118654752f;
#pragma unroll
    for (int mt = 0; mt < 4; mt++) {
        int rl = wm + mt * 16 + gid;          // local rows rl, rl+8
        float s0 = 0.f, s1 = 0.f, s2 = 0.f, s3 = 0.f;
#pragma unroll
        for (int nt = 0; nt < 4; nt++) {
            int c = wn + nt * 8 + 2 * tig;
            float bb0 = bias[c], bb1 = bias[c + 1];
            float v0 = acc[mt][nt][0] + bb0;
            float v1 = acc[mt][nt][1] + bb1;
            float v2 = acc[mt][nt][2] + bb0;
            float v3 = acc[mt][nt][3] + bb1;
            v0 = 0.5f * v0 * (1.0f + erff(v0 * is2));
            v1 = 0.5f * v1 * (1.0f + erff(v1 * is2));
            v2 = 0.5f * v2 * (1.0f + erff(v2 * is2));
            v3 = 0.5f * v3 * (1.0f + erff(v3 * is2));
            float4 w = *(const float4*)(w3 + c * 2);   // w3[c][0..1], w3[c+1][0..1]
            s0 += v0 * w.x + v1 * w.z;
            s1 += v0 * w.y + v1 * w.w;
            s2 += v2 * w.x + v3 * w.z;
            s3 += v2 * w.y + v3 * w.w;
        }
        atomicAdd(&sums[rl * 2 + 0], s0);
        atomicAdd(&sums[rl * 2 + 1], s1);
        atomicAdd(&sums[(rl + 8) * 2 + 0], s2);
        atomicAdd(&sums[(rl + 8) * 2 + 1], s3);
    }
    __syncthreads();

    int row = brow + (tid >> 1);
    if (row < M)
        out[(size_t)row * 2 + (tid & 1)] = sums[tid] + b3[tid & 1];
}

// ---------------------------------------------------------------------------
// Layer 1: ReLU + LN → fp32 h1 AND packed A-root (stride 2304)
// ---------------------------------------------------------------------------
__global__ void relu_ln1_kernel(const float* __restrict__ hp,
                                const float* __restrict__ g,
                                const float* __restrict__ b,
                                float* __restrict__ out) {
    int row = blockIdx.x;
    int tid = threadIdx.x;   // 256 == HID
    float v = fmaxf(hp[(size_t)row * HID + tid], 0.0f);

    __shared__ float red[8];
    __shared__ float s_mu, s_rs;

    float s = v;
#pragma unroll
    for (int o = 16; o; o >>= 1) s += __shfl_xor_sync(0xFFFFFFFFu, s, o);
    if ((tid & 31) == 0) red[tid >> 5] = s;
    __syncthreads();
    if (tid == 0) {
        float t = 0.f;
#pragma unroll
        for (int i = 0; i < 8; i++) t += red[i];
        s_mu = t / (float)HID;
    }
    __syncthreads();

    float d = v - s_mu;
    float s2 = d * d;
#pragma unroll
    for (int o = 16; o; o >>= 1) s2 += __shfl_xor_sync(0xFFFFFFFFu, s2, o);
    if ((tid & 31) == 0) red[tid >> 5] = s2;
    __syncthreads();
    if (tid == 0) {
        float t = 0.f;
#pragma unroll
        for (int i = 0; i < 8; i++) t += red[i];
        s_rs = rsqrtf(t / (float)HID + 1e-5f);
    }
    __syncthreads();

    float o = d * s_rs * g[tid] + b[tid];
    out[(size_t)row * HID + tid] = o;                       // fp32 h1 (dense)
    g_A[(size_t)row * 2304 + tid] = bf16_split_pack(o);     // packed A root
}

// Layer 2 variant: packed(resid + LN(relu(hp)))
__global__ void relu_ln_pack_kernel(const float* __restrict__ hp,
                                    const float* __restrict__ g,
                                    const float* __restrict__ b,
                                    uint32_t* __restrict__ outp,
                                    const float* __restrict__ resid) {
    int row = blockIdx.x;
    int tid = threadIdx.x;
    float v = fmaxf(hp[(size_t)row * HID + tid], 0.0f);

    __shared__ float red[8];
    __shared__ float s_mu, s_rs;

    float s = v;
#pragma unroll
    for (int o = 16; o; o >>= 1) s += __shfl_xor_sync(0xFFFFFFFFu, s, o);
    if ((tid & 31) == 0) red[tid >> 5] = s;
    __syncthreads();
    if (tid == 0) {
        float t = 0.f;
#pragma unroll
        for (int i = 0; i < 8; i++) t += red[i];
        s_mu = t / (float)HID;
    }
    __syncthreads();

    float d = v - s_mu;
    float s2 = d * d;
#pragma unroll
    for (int o = 16; o; o >>= 1) s2 += __shfl_xor_sync(0xFFFFFFFFu, s2, o);
    if ((tid & 31) == 0) red[tid >> 5] = s2;
    __syncthreads();
    if (tid == 0) {
        float t = 0.f;
#pragma unroll
        for (int i = 0; i < 8; i++) t += red[i];
        s_rs = rsqrtf(t / (float)HID + 1e-5f);
    }
    __syncthreads();

    float o = d * s_rs * g[tid] + b[tid] + resid[(size_t)row * HID + tid];
    outp[(size_t)row * HID + tid] = bf16_split_pack(o);
}

// ---------------------------------------------------------------------------
// Fused decoder stage 1: Z1[m,c] = packed(gelu(P[u][c] + P[v][256+c] + b1[c]))
// ---------------------------------------------------------------------------
__global__ void decode_fuse_kernel(const int* __restrict__ dec,
                                   const float* __restrict__ b1) {
    int idx = blockIdx.x * blockDim.x + threadIdx.x;
    if (idx >= M_DEC * (HID / 4)) return;
    int m = idx >> 6;
    int j = idx & 63;
    int u = dec[m * 2 + 0];
    int v = dec[m * 2 + 1];
    float4 p = __ldg((const float4*)(g_P + (size_t)u * 512) + j);
    float4 q = __ldg((const float4*)(g_P + (size_t)v * 512 + 256) + j);
    float4 bb = *((const float4*)b1 + j);
    const float is2 = 0.70710678118654752f;
    float zx = p.x + q.x + bb.x; zx = 0.5f * zx * (1.0f + erff(zx * is2));
    float zy = p.y + q.y + bb.y; zy = 0.5f * zy * (1.0f + erff(zy * is2));
    float zz = p.z + q.z + bb.z; zz = 0.5f * zz * (1.0f + erff(zz * is2));
    float zw = p.w + q.w + bb.w; zw = 0.5f * zw * (1.0f + erff(zw * is2));
    uint4 o;
    o.x = bf16_split_pack(zx);
    o.y = bf16_split_pack(zy);
    o.z = bf16_split_pack(zz);
    o.w = bf16_split_pack(zw);
    *((uint4*)(g_Z1 + (size_t)m * HID) + j) = o;
}

// ---------------------------------------------------------------------------
static inline int blocks_for(long long n, int bs) { return (int)((n + bs - 1) / bs); }

extern "C" void kernel_launch(void* const* d_in, const int* in_sizes, int n_in,
                              void* d_out, int out_size) {
    const float* x     = (const float*)d_in[0];
    const int*   ei    = (const int*)  d_in[1];
    const int*   et    = (const int*)  d_in[2];
    const int*   dec   = (const int*)  d_in[3];
    const float* W1    = (const float*)d_in[4];
    const float* root1 = (const float*)d_in[5];
    const float* b1    = (const float*)d_in[6];
    const float* W2    = (const float*)d_in[7];
    const float* root2 = (const float*)d_in[8];
    const float* b2    = (const float*)d_in[9];
    const float* ln1g  = (const float*)d_in[10];
    const float* ln1b  = (const float*)d_in[11];
    const float* ln2g  = (const float*)d_in[12];
    const float* ln2b  = (const float*)d_in[13];
    const float* mw1   = (const float*)d_in[14];
    const float* mb1   = (const float*)d_in[15];
    const float* mw2   = (const float*)d_in[16];
    const float* mb2   = (const float*)d_in[17];
    const float* mw3   = (const float*)d_in[18];
    const float* mb3   = (const float*)d_in[19];
    float* out = (float*)d_out;

    uint32_t *A, *B1p, *B2p, *Bd, *Bw2, *hP, *Z1;
    float *hp, *h1, *P;
    int *deg, *off, *cur;
    cudaGetSymbolAddress((void**)&A,   g_A);
    cudaGetSymbolAddress((void**)&B1p, g_B1);
    cudaGetSymbolAddress((void**)&B2p, g_B2);
    cudaGetSymbolAddress((void**)&Bd,  g_Bd);
    cudaGetSymbolAddress((void**)&Bw2, g_Bw2);
    cudaGetSymbolAddress((void**)&hP,  g_hP);
    cudaGetSymbolAddress((void**)&Z1,  g_Z1);
    cudaGetSymbolAddress((void**)&hp,  g_hp);
    cudaGetSymbolAddress((void**)&h1,  g_h1);
    cudaGetSymbolAddress((void**)&P,   g_P);
    cudaGetSymbolAddress((void**)&deg, g_deg);
    cudaGetSymbolAddress((void**)&off, g_off);
    cudaGetSymbolAddress((void**)&cur, g_cur);

    // ===================== CSR build =====================
    zero_int_kernel<<<blocks_for(NKEYS / 4, 256), 256>>>(deg, NKEYS / 4);
    hist_kernel<<<blocks_for(E_EDGES, 256), 256>>>(ei, et);
    int nblk = (NKEYS + 1023) / 1024;
    scan1_kernel<<<nblk, 256>>>(deg, off, NKEYS);
    scan2_kernel<<<1, 512>>>(nblk);
    scan3_kernel<<<blocks_for(NKEYS, 256), 256>>>(off, cur, NKEYS);
    fill_kernel<<<blocks_for(E_EDGES, 256), 256>>>(ei, et);

    // ===================== Weight packs + layer-1 root =====================
    copy_feat1_kernel<<<blocks_for(N_NODES * (IN_DIM / 4), 256), 256>>>(x);
    build_B_kernel<<<blocks_for(1152 * HID, 256), 256>>>(root1, W1, IN_DIM, B1p);
    build_B_kernel<<<blocks_for(2304 * HID, 256), 256>>>(root2, W2, HID, B2p);
    build_Bdec_kernel<<<blocks_for(2 * HID * HID, 256), 256>>>(mw1);
    pack_w2_kernel<<<blocks_for(HID * (HID / 2), 256), 256>>>(mw2);

    // ===================== Layer 1 (K = 1152) =====================
    gather_agg_kernel<IN_DIM><<<blocks_for((long long)NKEYS * 32, 256), 256>>>(x);
    {
        dim3 grid(HID / 128, (N_NODES + 127) / 128);
        gemm_ps_kernel<<<grid, 256>>>(A, B1p, hp, b1, N_NODES, HID, 1152, 0);
    }
    relu_ln1_kernel<<<N_NODES, HID>>>(hp, ln1g, ln1b, h1);   // also packs A root

    // ===================== Layer 2 (K = 2304) =====================
    gather_agg_kernel<HID><<<blocks_for((long long)NKEYS * 32, 256), 256>>>(h1);
    {
        dim3 grid(HID / 128, (N_NODES + 127) / 128);
        gemm_ps_kernel<<<grid, 256>>>(A, B2p, hp, b2, N_NODES, HID, 2304, 0);
    }
    relu_ln_pack_kernel<<<N_NODES, HID>>>(hp, ln2g, ln2b, hP, h1);

    // ===================== Decoder =====================
    {
        dim3 gp(4, (N_NODES + 127) / 128);
        gemm_ps_kernel<<<gp, 256>>>(hP, Bd, P, nullptr, N_NODES, 2 * HID, HID, 0);

        decode_fuse_kernel<<<blocks_for((long long)M_DEC * (HID / 4), 256), 256>>>(dec, mb1);

        // Fused: out = gelu(Z1 @ mw2 + mb2) @ mw3 + mb3
        dim3 g2(1, (M_DEC + 127) / 128);
        gemm_z2_final_kernel<<<g2, 256>>>(Z1, Bw2, mb2, mw3, mb3, out, M_DEC, HID);
    }
}